// round 2
// baseline (speedup 1.0000x reference)
#include <cuda_runtime.h>
#include <cstdint>

// IDWT (inverse Haar wavelet). Inputs LL,LH,HL,HH: [B=16,C=64,h=128,w=128] f32.
// Output: [B,C,256,256] f32. Closed-form 2x2 butterfly, s^2 = 0.5.
//
// Each thread: TWO adjacent float4s of each input (8 consecutive j in one row),
// emits 2 rows x 16 cols = 4 contiguous float4 per row.
// 8 front-batched LDG.128 (MLP_p1=8), streaming cache hints on both sides.

static constexpr int NROWS = 16 * 64 * 128;        // B*C*h = 131072
static constexpr int PAIRS_PER_ROW = 16;           // (w/4)/2
static constexpr int NTHREADS_TOTAL = NROWS * PAIRS_PER_ROW;  // 2,097,152

__device__ __forceinline__ void butterfly(const float4& ll, const float4& lh,
                                          const float4& hl, const float4& hh,
                                          float4& t0, float4& t1,
                                          float4& b0, float4& b1)
{
    // columns x..w -> output cols 2k, 2k+1 (top row) and same (bottom row)
    t0.x = 0.5f * (ll.x - lh.x - hl.x + hh.x);
    t0.y = 0.5f * (ll.x + lh.x - hl.x - hh.x);
    t0.z = 0.5f * (ll.y - lh.y - hl.y + hh.y);
    t0.w = 0.5f * (ll.y + lh.y - hl.y - hh.y);
    t1.x = 0.5f * (ll.z - lh.z - hl.z + hh.z);
    t1.y = 0.5f * (ll.z + lh.z - hl.z - hh.z);
    t1.z = 0.5f * (ll.w - lh.w - hl.w + hh.w);
    t1.w = 0.5f * (ll.w + lh.w - hl.w - hh.w);

    b0.x = 0.5f * (ll.x - lh.x + hl.x - hh.x);
    b0.y = 0.5f * (ll.x + lh.x + hl.x + hh.x);
    b0.z = 0.5f * (ll.y - lh.y + hl.y - hh.y);
    b0.w = 0.5f * (ll.y + lh.y + hl.y + hh.y);
    b1.x = 0.5f * (ll.z - lh.z + hl.z - hh.z);
    b1.y = 0.5f * (ll.z + lh.z + hl.z + hh.z);
    b1.z = 0.5f * (ll.w - lh.w + hl.w - hh.w);
    b1.w = 0.5f * (ll.w + lh.w + hl.w + hh.w);
}

__global__ __launch_bounds__(256) void idwt_haar_kernel(
    const float4* __restrict__ LL,
    const float4* __restrict__ LH,
    const float4* __restrict__ HL,
    const float4* __restrict__ HH,
    float4* __restrict__ out)
{
    int tid = blockIdx.x * blockDim.x + threadIdx.x;
    if (tid >= NTHREADS_TOTAL) return;

    int q0 = tid * 2;          // first input float4 index
    int q1 = q0 + 1;

    // Front-batch all 8 loads (independent -> deep MLP), streaming hint.
    float4 ll0 = __ldcs(&LL[q0]);
    float4 lh0 = __ldcs(&LH[q0]);
    float4 hl0 = __ldcs(&HL[q0]);
    float4 hh0 = __ldcs(&HH[q0]);
    float4 ll1 = __ldcs(&LL[q1]);
    float4 lh1 = __ldcs(&LH[q1]);
    float4 hl1 = __ldcs(&HL[q1]);
    float4 hh1 = __ldcs(&HH[q1]);

    int row = tid >> 4;        // bc*128 + i  (16 pairs per row)
    int p   = tid & 15;        // pair index within the row

    int bc = row >> 7;
    int i  = row & 127;

    // output [bc][256][256] f32 -> float4 row stride 64.
    // pair p covers input cols 8p..8p+7 -> output cols 16p..16p+15
    // = float4 indices 4p..4p+3 in rows 2i and 2i+1.
    size_t obase = ((size_t)bc * 256 + 2 * i) * 64 + (size_t)p * 4;

    float4 t0, t1, t2, t3, b0, b1, b2, b3;
    butterfly(ll0, lh0, hl0, hh0, t0, t1, b0, b1);
    butterfly(ll1, lh1, hl1, hh1, t2, t3, b2, b3);

    __stcs(&out[obase + 0], t0);
    __stcs(&out[obase + 1], t1);
    __stcs(&out[obase + 2], t2);
    __stcs(&out[obase + 3], t3);
    __stcs(&out[obase + 64 + 0], b0);
    __stcs(&out[obase + 64 + 1], b1);
    __stcs(&out[obase + 64 + 2], b2);
    __stcs(&out[obase + 64 + 3], b3);
}

extern "C" void kernel_launch(void* const* d_in, const int* in_sizes, int n_in,
                              void* d_out, int out_size)
{
    const float4* LL = (const float4*)d_in[0];
    const float4* LH = (const float4*)d_in[1];
    const float4* HL = (const float4*)d_in[2];
    const float4* HH = (const float4*)d_in[3];

    float4* out = (float4*)d_out;

    int threads = 256;
    int blocks = NTHREADS_TOTAL / threads;  // 8192
    idwt_haar_kernel<<<blocks, threads>>>(LL, LH, HL, HH, out);
}

// round 3
// speedup vs baseline: 1.1049x; 1.1049x over previous
#include <cuda_runtime.h>
#include <cstdint>

// IDWT (inverse Haar wavelet). Inputs LL,LH,HL,HH: [B=16,C=64,h=128,w=128] f32.
// Output: [B,C,256,256] f32. Closed-form 2x2 butterfly, s^2 = 0.5.
//
// R1 structure (1 float4 per thread, max occupancy) + streaming cache hints.

static constexpr int W4 = 32;                      // w/4
static constexpr int NROWS = 16 * 64 * 128;        // B*C*h = 131072
static constexpr int NTHREADS_TOTAL = NROWS * W4;  // 4,194,304

__global__ __launch_bounds__(256) void idwt_haar_kernel(
    const float4* __restrict__ LL,
    const float4* __restrict__ LH,
    const float4* __restrict__ HL,
    const float4* __restrict__ HH,
    float4* __restrict__ out)
{
    int tid = blockIdx.x * blockDim.x + threadIdx.x;
    if (tid >= NTHREADS_TOTAL) return;

    float4 ll = __ldcs(&LL[tid]);
    float4 lh = __ldcs(&LH[tid]);
    float4 hl = __ldcs(&HL[tid]);
    float4 hh = __ldcs(&HH[tid]);

    int row = tid >> 5;        // bc*128 + i
    int jq  = tid & 31;

    int bc = row >> 7;
    int i  = row & 127;

    size_t obase = ((size_t)bc * 256 + 2 * i) * 64 + (size_t)jq * 2;

    float4 t0, t1, b0, b1;
    t0.x = 0.5f * (ll.x - lh.x - hl.x + hh.x);
    t0.y = 0.5f * (ll.x + lh.x - hl.x - hh.x);
    t0.z = 0.5f * (ll.y - lh.y - hl.y + hh.y);
    t0.w = 0.5f * (ll.y + lh.y - hl.y - hh.y);
    t1.x = 0.5f * (ll.z - lh.z - hl.z + hh.z);
    t1.y = 0.5f * (ll.z + lh.z - hl.z - hh.z);
    t1.z = 0.5f * (ll.w - lh.w - hl.w + hh.w);
    t1.w = 0.5f * (ll.w + lh.w - hl.w - hh.w);

    b0.x = 0.5f * (ll.x - lh.x + hl.x - hh.x);
    b0.y = 0.5f * (ll.x + lh.x + hl.x + hh.x);
    b0.z = 0.5f * (ll.y - lh.y + hl.y - hh.y);
    b0.w = 0.5f * (ll.y + lh.y + hl.y + hh.y);
    b1.x = 0.5f * (ll.z - lh.z + hl.z - hh.z);
    b1.y = 0.5f * (ll.z + lh.z + hl.z + hh.z);
    b1.z = 0.5f * (ll.w - lh.w + hl.w - hh.w);
    b1.w = 0.5f * (ll.w + lh.w + hl.w + hh.w);

    __stcs(&out[obase + 0], t0);
    __stcs(&out[obase + 1], t1);
    __stcs(&out[obase + 64 + 0], b0);
    __stcs(&out[obase + 64 + 1], b1);
}

extern "C" void kernel_launch(void* const* d_in, const int* in_sizes, int n_in,
                              void* d_out, int out_size)
{
    const float4* LL = (const float4*)d_in[0];
    const float4* LH = (const float4*)d_in[1];
    const float4* HL = (const float4*)d_in[2];
    const float4* HH = (const float4*)d_in[3];

    float4* out = (float4*)d_out;

    int threads = 256;
    int blocks = NTHREADS_TOTAL / threads;  // 16384
    idwt_haar_kernel<<<blocks, threads>>>(LL, LH, HL, HH, out);
}